// round 6
// baseline (speedup 1.0000x reference)
#include <cuda_runtime.h>
#include <math.h>

#define Bb   128
#define Ss   1024
#define IND  256
#define MM   64
#define DD   128
#define OUTD 128
#define ROWS (Bb*Ss)   // 131072

typedef unsigned long long u64;

__device__ __forceinline__ u64 pk2(float lo, float hi) {
    u64 r; asm("mov.b64 %0,{%1,%2};" : "=l"(r) : "f"(lo), "f"(hi)); return r;
}
__device__ __forceinline__ void upk2(float& lo, float& hi, u64 v) {
    asm("mov.b64 {%0,%1},%2;" : "=f"(lo), "=f"(hi) : "l"(v));
}
__device__ __forceinline__ u64 fma2(u64 a, u64 b, u64 c) {
    u64 d; asm("fma.rn.f32x2 %0,%1,%2,%3;" : "=l"(d) : "l"(a), "l"(b), "l"(c)); return d;
}
__device__ __forceinline__ u64 mul2(u64 a, u64 b) {
    u64 d; asm("mul.rn.f32x2 %0,%1,%2;" : "=l"(d) : "l"(a), "l"(b)); return d;
}
__device__ __forceinline__ u64 add2(u64 a, u64 b) {
    u64 d; asm("add.rn.f32x2 %0,%1,%2;" : "=l"(d) : "l"(a), "l"(b)); return d;
}

// ---------------- scratch ----------------
__device__ __align__(16) float g_Wk2[IND*MM];
__device__ __align__(16) float g_bk2[MM];
__device__ __align__(16) float g_wd[(size_t)ROWS*2*MM];  // w duplicated (w,w) pairs  67MB
__device__ __align__(16) float g_e[(size_t)ROWS*DD];     // -sigmoid(v)               67MB
__device__ __align__(16) float g_a[(size_t)ROWS*DD];     // tanh(v)                   67MB
__device__ __align__(16) float g_r[(size_t)ROWS*DD];     // read vectors              67MB

// ---------------- K0 ----------------
__global__ void k0_fold(const float* __restrict__ Wr, const float* __restrict__ br,
                        const float* __restrict__ Mk) {
    int gid = blockIdx.x * 256 + threadIdx.x;
    if (gid < IND*MM) {
        int i = gid >> 6, m = gid & 63;
        const float* wr = Wr + (size_t)i * DD;
        const float* mk = Mk + (size_t)m * DD;
        float s = 0.f;
        #pragma unroll 8
        for (int d = 0; d < DD; d++) s = fmaf(wr[d], mk[d], s);
        g_Wk2[i*MM + m] = s;
    } else if (gid < IND*MM + MM) {
        int m = gid - IND*MM;
        const float* mk = Mk + (size_t)m * DD;
        float s = 0.f;
        #pragma unroll 8
        for (int d = 0; d < DD; d++) s = fmaf(br[d], mk[d], s);
        g_bk2[m] = s;
    }
}

// ---------------- K1a: w = softmax(x @ Wk2 + bk2); writes duplicated pairs ----------------
__global__ __launch_bounds__(256) void k1a_wsoftmax(const float* __restrict__ x) {
    __shared__ float As[16][128];
    __shared__ u64   Bs2[16][32];
    __shared__ float sC[128][65];
    __shared__ float rmax[128], rinv[128];

    int tid = threadIdx.x;
    int tx = tid & 15;
    int ty = tid >> 4;
    int rowBase = blockIdx.x * 128;

    u64 acc2[8][2];
    #pragma unroll
    for (int i = 0; i < 8; i++) { acc2[i][0] = 0ull; acc2[i][1] = 0ull; }

    for (int kb = 0; kb < IND; kb += 16) {
        #pragma unroll
        for (int it = 0; it < 2; it++) {
            int f4 = tid + it * 256;
            int row = f4 >> 2, kk4 = f4 & 3;
            float4 v = *(const float4*)(x + (size_t)(rowBase + row) * IND + kb + kk4 * 4);
            As[kk4*4+0][row] = v.x; As[kk4*4+1][row] = v.y;
            As[kk4*4+2][row] = v.z; As[kk4*4+3][row] = v.w;
        }
        {
            int k = tid >> 4, n4 = tid & 15;
            float4 v = *(const float4*)(g_Wk2 + (size_t)(kb + k) * MM + n4 * 4);
            Bs2[k][n4*2+0] = pk2(v.x, v.y);
            Bs2[k][n4*2+1] = pk2(v.z, v.w);
        }
        __syncthreads();
        #pragma unroll
        for (int k = 0; k < 16; k++) {
            u64 rb0 = Bs2[k][tx];
            u64 rb1 = Bs2[k][tx + 16];
            #pragma unroll
            for (int i = 0; i < 8; i++) {
                float a = As[k][ty*8 + i];
                u64 a2 = pk2(a, a);
                acc2[i][0] = fma2(a2, rb0, acc2[i][0]);
                acc2[i][1] = fma2(a2, rb1, acc2[i][1]);
            }
        }
        __syncthreads();
    }
    float acc[8][4];
    float b0 = g_bk2[2*tx], b1 = g_bk2[2*tx+1], b2 = g_bk2[2*tx+32], b3 = g_bk2[2*tx+33];
    #pragma unroll
    for (int i = 0; i < 8; i++) {
        float lo, hi;
        upk2(lo, hi, acc2[i][0]);
        acc[i][0] = lo + b0; acc[i][1] = hi + b1;
        upk2(lo, hi, acc2[i][1]);
        acc[i][2] = lo + b2; acc[i][3] = hi + b3;
        int row = ty*8 + i;
        sC[row][2*tx]    = acc[i][0];
        sC[row][2*tx+1]  = acc[i][1];
        sC[row][2*tx+32] = acc[i][2];
        sC[row][2*tx+33] = acc[i][3];
    }
    __syncthreads();
    {
        int row = tid >> 1, h = tid & 1;
        float mx = -1e30f;
        #pragma unroll 8
        for (int i = 0; i < 32; i++) mx = fmaxf(mx, sC[row][h*32 + i]);
        mx = fmaxf(mx, __shfl_xor_sync(0xffffffffu, mx, 1));
        float s = 0.f;
        #pragma unroll 8
        for (int i = 0; i < 32; i++) s += expf(sC[row][h*32 + i] - mx);
        s += __shfl_xor_sync(0xffffffffu, s, 1);
        if (!h) { rmax[row] = mx; rinv[row] = 1.f / s; }
    }
    __syncthreads();
    #pragma unroll
    for (int i = 0; i < 8; i++) {
        int row = ty*8 + i;
        float m = rmax[row], inv = rinv[row];
        float* wd = g_wd + (size_t)(rowBase + row) * (2*MM);
        float w0 = expf(acc[i][0]-m)*inv;
        float w1 = expf(acc[i][1]-m)*inv;
        float w2 = expf(acc[i][2]-m)*inv;
        float w3 = expf(acc[i][3]-m)*inv;
        float4 p0; p0.x = w0; p0.y = w0; p0.z = w1; p0.w = w1;
        float4 p1; p1.x = w2; p1.y = w2; p1.z = w3; p1.w = w3;
        *(float4*)(wd + 4*tx)      = p0;   // m = 2tx, 2tx+1 duplicated
        *(float4*)(wd + 4*tx + 64) = p1;   // m = 2tx+32, 2tx+33 duplicated
    }
}

// ---------------- K1b: v = x @ Ww + bw ; stores -sigmoid(v) and tanh(v) ----------------
__global__ __launch_bounds__(256) void k1b_ea(const float* __restrict__ x,
                                              const float* __restrict__ Ww,
                                              const float* __restrict__ bw) {
    __shared__ float As[16][128];
    __shared__ u64   Bs2[16][64];
    int tid = threadIdx.x;
    int tx = tid & 15;
    int ty = tid >> 4;
    int rowBase = blockIdx.x * 128;

    u64 acc2[8][4];
    #pragma unroll
    for (int i = 0; i < 8; i++)
        #pragma unroll
        for (int j = 0; j < 4; j++) acc2[i][j] = 0ull;

    for (int kb = 0; kb < IND; kb += 16) {
        #pragma unroll
        for (int it = 0; it < 2; it++) {
            int f4 = tid + it * 256;
            int row = f4 >> 2, kk4 = f4 & 3;
            float4 v = *(const float4*)(x + (size_t)(rowBase + row) * IND + kb + kk4 * 4);
            As[kk4*4+0][row] = v.x; As[kk4*4+1][row] = v.y;
            As[kk4*4+2][row] = v.z; As[kk4*4+3][row] = v.w;
        }
        #pragma unroll
        for (int it = 0; it < 2; it++) {
            int f4 = tid + it * 256;
            int k = f4 >> 5, n4 = f4 & 31;
            float4 v = *(const float4*)(Ww + (size_t)(kb + k) * DD + n4 * 4);
            Bs2[k][n4*2+0] = pk2(v.x, v.y);
            Bs2[k][n4*2+1] = pk2(v.z, v.w);
        }
        __syncthreads();
        #pragma unroll
        for (int k = 0; k < 16; k++) {
            u64 rb[4];
            #pragma unroll
            for (int j = 0; j < 4; j++) rb[j] = Bs2[k][tx + 16*j];
            #pragma unroll
            for (int i = 0; i < 8; i++) {
                float a = As[k][ty*8 + i];
                u64 a2 = pk2(a, a);
                #pragma unroll
                for (int j = 0; j < 4; j++) acc2[i][j] = fma2(a2, rb[j], acc2[i][j]);
            }
        }
        __syncthreads();
    }
    float blo[4], bhi[4];
    #pragma unroll
    for (int j = 0; j < 4; j++) {
        int c = 2*(tx + 16*j);
        blo[j] = bw[c]; bhi[j] = bw[c+1];
    }
    #pragma unroll
    for (int i = 0; i < 8; i++) {
        size_t row = (size_t)(rowBase + ty*8 + i);
        #pragma unroll
        for (int j = 0; j < 4; j++) {
            float lo, hi;
            upk2(lo, hi, acc2[i][j]);
            float v0 = lo + blo[j], v1 = hi + bhi[j];
            int c = 2*(tx + 16*j);
            *(u64*)(g_e + row*DD + c) = pk2(-1.f/(1.f+expf(-v0)), -1.f/(1.f+expf(-v1)));
            *(u64*)(g_a + row*DD + c) = pk2(tanhf(v0), tanhf(v1));
        }
    }
}

// ---------------- K2: scan, 512 thr, short-critical-path recurrence ----------------
// CTA = batch. 16 warps; warp owns d [warp*8, warp*8+8).
// lane: dp = lane&3 -> d-pair (d0 = warp*8 + dp*2); mq = lane>>2 -> m in [mq*8, mq*8+8)
// Recurrence per element:  u = 1 - w*e (fma, Mv-independent), wa = w*a (mul, Mv-independent)
//                          r += w*Mv_old (fma), Mv = fma(Mv, u, wa)  -> 4cyc cross-step chain
__global__ __launch_bounds__(512) void k2_scan(const float* __restrict__ mv0) {
    int b = blockIdx.x;
    int warp = threadIdx.x >> 5, lane = threadIdx.x & 31;
    int dp = lane & 3, mq = lane >> 2;
    int d0 = warp * 8 + dp * 2;
    int m0 = mq * 8;

    const float* wdp = g_wd + (size_t)b * Ss * (2*MM) + 2*m0;
    const float* ep  = g_e  + (size_t)b * Ss * DD + d0;
    const float* ap  = g_a  + (size_t)b * Ss * DD + d0;
    float*       rp  = g_r  + (size_t)b * Ss * DD + d0;

    const u64 ONE2 = pk2(1.f, 1.f);

    u64 Mv[8];
    #pragma unroll
    for (int j = 0; j < 8; j++)
        Mv[j] = *(const u64*)(mv0 + (size_t)(m0 + j) * DD + d0);

    longlong2 wb[2][4];
    u64 e2v[2], a2v[2];

#define FETCH(T, S) do { \
        const longlong2* wt = (const longlong2*)(wdp + (size_t)(T) * (2*MM)); \
        wb[S][0] = wt[0]; wb[S][1] = wt[1]; wb[S][2] = wt[2]; wb[S][3] = wt[3]; \
        e2v[S] = *(const u64*)(ep + (size_t)(T) * DD); \
        a2v[S] = *(const u64*)(ap + (size_t)(T) * DD); \
    } while (0)

    FETCH(0, 0);
    FETCH(1, 1);

    u64 rprev = 0ull;

    for (int t = 0; t < Ss; t += 2) {
        #pragma unroll
        for (int s = 0; s < 2; s++) {
            u64 en2 = e2v[s];     // already negated sigmoid
            u64 a2c = a2v[s];
            u64 w0 = (u64)wb[s][0].x, w1 = (u64)wb[s][0].y;
            u64 w2 = (u64)wb[s][1].x, w3 = (u64)wb[s][1].y;
            u64 w4 = (u64)wb[s][2].x, w5 = (u64)wb[s][2].y;
            u64 w6 = (u64)wb[s][3].x, w7 = (u64)wb[s][3].y;
            if (t + s + 2 < Ss) FETCH(t + s + 2, s);

            // deferred finalize of PREVIOUS step's r: shfl latency overlaps
            // the Mv-independent u/wa precompute below
            u64 p = rprev;
            p = add2(p, __shfl_xor_sync(0xffffffffu, p, 4));

            // u_j / wa_j: independent of Mv
            u64 u0 = fma2(w0, en2, ONE2), wa0 = mul2(w0, a2c);
            u64 u1 = fma2(w1, en2, ONE2), wa1 = mul2(w1, a2c);
            u64 u2 = fma2(w2, en2, ONE2), wa2 = mul2(w2, a2c);
            u64 u3 = fma2(w3, en2, ONE2), wa3 = mul2(w3, a2c);
            u64 u4 = fma2(w4, en2, ONE2), wa4 = mul2(w4, a2c);
            u64 u5 = fma2(w5, en2, ONE2), wa5 = mul2(w5, a2c);
            u64 u6 = fma2(w6, en2, ONE2), wa6 = mul2(w6, a2c);
            u64 u7 = fma2(w7, en2, ONE2), wa7 = mul2(w7, a2c);

            p = add2(p, __shfl_xor_sync(0xffffffffu, p, 8));

            // r from old Mv (2 accumulator chains), then 1-fma Mv update
            u64 r0 = mul2(w0, Mv[0]);
            u64 r1 = mul2(w1, Mv[1]);
            Mv[0] = fma2(Mv[0], u0, wa0);
            Mv[1] = fma2(Mv[1], u1, wa1);
            r0 = fma2(w2, Mv[2], r0);
            r1 = fma2(w3, Mv[3], r1);
            Mv[2] = fma2(Mv[2], u2, wa2);
            Mv[3] = fma2(Mv[3], u3, wa3);
            r0 = fma2(w4, Mv[4], r0);
            r1 = fma2(w5, Mv[5], r1);
            Mv[4] = fma2(Mv[4], u4, wa4);
            Mv[5] = fma2(Mv[5], u5, wa5);
            r0 = fma2(w6, Mv[6], r0);
            r1 = fma2(w7, Mv[7], r1);
            Mv[6] = fma2(Mv[6], u6, wa6);
            Mv[7] = fma2(Mv[7], u7, wa7);

            p = add2(p, __shfl_xor_sync(0xffffffffu, p, 16));
            if ((t + s) > 0 && mq == 0)
                *(u64*)(rp + (size_t)(t + s - 1) * DD) = p;

            rprev = add2(r0, r1);
        }
    }
    // tail: finalize last step
    {
        u64 p = rprev;
        p = add2(p, __shfl_xor_sync(0xffffffffu, p, 4));
        p = add2(p, __shfl_xor_sync(0xffffffffu, p, 8));
        p = add2(p, __shfl_xor_sync(0xffffffffu, p, 16));
        if (mq == 0)
            *(u64*)(rp + (size_t)(Ss - 1) * DD) = p;
    }
#undef FETCH
}

// ---------------- K3: y = sigmoid(r @ Wp + bp) ----------------
__global__ __launch_bounds__(256) void k3_out(const float* __restrict__ Wp,
                                              const float* __restrict__ bp,
                                              float* __restrict__ out) {
    __shared__ float As[16][128];
    __shared__ u64   Bs2[16][64];
    int tid = threadIdx.x;
    int tx = tid & 15;
    int ty = tid >> 4;
    int rowBase = blockIdx.x * 128;

    u64 acc2[8][4];
    #pragma unroll
    for (int i = 0; i < 8; i++)
        #pragma unroll
        for (int j = 0; j < 4; j++) acc2[i][j] = 0ull;

    for (int kb = 0; kb < DD; kb += 16) {
        #pragma unroll
        for (int it = 0; it < 2; it++) {
            int f4 = tid + it * 256;
            int row = f4 >> 2, kk4 = f4 & 3;
            float4 v = *(const float4*)(g_r + (size_t)(rowBase + row) * DD + kb + kk4 * 4);
            As[kk4*4+0][row] = v.x; As[kk4*4+1][row] = v.y;
            As[kk4*4+2][row] = v.z; As[kk4*4+3][row] = v.w;
        }
        #pragma unroll
        for (int it = 0; it < 2; it++) {
            int f4 = tid + it * 256;
            int k = f4 >> 5, n4 = f4 & 31;
            float4 v = *(const float4*)(Wp + (size_t)(kb + k) * OUTD + n4 * 4);
            Bs2[k][n4*2+0] = pk2(v.x, v.y);
            Bs2[k][n4*2+1] = pk2(v.z, v.w);
        }
        __syncthreads();
        #pragma unroll
        for (int k = 0; k < 16; k++) {
            u64 rb[4];
            #pragma unroll
            for (int j = 0; j < 4; j++) rb[j] = Bs2[k][tx + 16*j];
            #pragma unroll
            for (int i = 0; i < 8; i++) {
                float a = As[k][ty*8 + i];
                u64 a2 = pk2(a, a);
                #pragma unroll
                for (int j = 0; j < 4; j++) acc2[i][j] = fma2(a2, rb[j], acc2[i][j]);
            }
        }
        __syncthreads();
    }
    float blo[4], bhi[4];
    #pragma unroll
    for (int j = 0; j < 4; j++) {
        int c = 2*(tx + 16*j);
        blo[j] = bp[c]; bhi[j] = bp[c+1];
    }
    #pragma unroll
    for (int i = 0; i < 8; i++) {
        size_t row = (size_t)(rowBase + ty*8 + i);
        #pragma unroll
        for (int j = 0; j < 4; j++) {
            float lo, hi;
            upk2(lo, hi, acc2[i][j]);
            float v0 = lo + blo[j], v1 = hi + bhi[j];
            int c = 2*(tx + 16*j);
            *(u64*)(out + row*OUTD + c) = pk2(1.f/(1.f+expf(-v0)), 1.f/(1.f+expf(-v1)));
        }
    }
}

// ---------------- launch ----------------
extern "C" void kernel_launch(void* const* d_in, const int* in_sizes, int n_in,
                              void* d_out, int out_size) {
    const float* x   = (const float*)d_in[0];
    const float* Mk  = (const float*)d_in[1];
    const float* Mv0 = (const float*)d_in[2];
    const float* Wr  = (const float*)d_in[3];
    const float* br  = (const float*)d_in[4];
    const float* Ww  = (const float*)d_in[5];
    const float* bw  = (const float*)d_in[6];
    const float* Wp  = (const float*)d_in[7];
    const float* bp  = (const float*)d_in[8];
    float* out = (float*)d_out;

    k0_fold<<<65, 256>>>(Wr, br, Mk);
    k1a_wsoftmax<<<ROWS/128, 256>>>(x);
    k1b_ea<<<ROWS/128, 256>>>(x, Ww, bw);
    k2_scan<<<Bb, 512>>>(Mv0);
    k3_out<<<ROWS/128, 256>>>(Wp, bp, out);
}

// round 8
// speedup vs baseline: 1.5170x; 1.5170x over previous
#include <cuda_runtime.h>
#include <math.h>

#define Bb   128
#define Ss   1024
#define IND  256
#define MM   64
#define DD   128
#define OUTD 128
#define ROWS (Bb*Ss)   // 131072

typedef unsigned long long u64;

__device__ __forceinline__ u64 pk2(float lo, float hi) {
    u64 r; asm("mov.b64 %0,{%1,%2};" : "=l"(r) : "f"(lo), "f"(hi)); return r;
}
__device__ __forceinline__ void upk2(float& lo, float& hi, u64 v) {
    asm("mov.b64 {%0,%1},%2;" : "=f"(lo), "=f"(hi) : "l"(v));
}
__device__ __forceinline__ u64 fma2(u64 a, u64 b, u64 c) {
    u64 d; asm("fma.rn.f32x2 %0,%1,%2,%3;" : "=l"(d) : "l"(a), "l"(b), "l"(c)); return d;
}
__device__ __forceinline__ u64 mul2(u64 a, u64 b) {
    u64 d; asm("mul.rn.f32x2 %0,%1,%2;" : "=l"(d) : "l"(a), "l"(b)); return d;
}
__device__ __forceinline__ u64 add2(u64 a, u64 b) {
    u64 d; asm("add.rn.f32x2 %0,%1,%2;" : "=l"(d) : "l"(a), "l"(b)); return d;
}

// ---------------- scratch ----------------
__device__ __align__(16) float g_Wk2[IND*MM];
__device__ __align__(16) float g_bk2[MM];
__device__ __align__(16) float g_wd[(size_t)ROWS*2*MM];   // w duplicated (w,w) pairs 67MB
__device__ __align__(16) float g_ea[(size_t)ROWS*2*DD];   // interleaved {-sig pair, tanh pair} per d-pair 134MB
__device__ __align__(16) float g_r[(size_t)ROWS*DD];      // read vectors             67MB

// ---------------- K0 ----------------
__global__ void k0_fold(const float* __restrict__ Wr, const float* __restrict__ br,
                        const float* __restrict__ Mk) {
    int gid = blockIdx.x * 256 + threadIdx.x;
    if (gid < IND*MM) {
        int i = gid >> 6, m = gid & 63;
        const float* wr = Wr + (size_t)i * DD;
        const float* mk = Mk + (size_t)m * DD;
        float s = 0.f;
        #pragma unroll 8
        for (int d = 0; d < DD; d++) s = fmaf(wr[d], mk[d], s);
        g_Wk2[i*MM + m] = s;
    } else if (gid < IND*MM + MM) {
        int m = gid - IND*MM;
        const float* mk = Mk + (size_t)m * DD;
        float s = 0.f;
        #pragma unroll 8
        for (int d = 0; d < DD; d++) s = fmaf(br[d], mk[d], s);
        g_bk2[m] = s;
    }
}

// ---------------- K1a: w = softmax(x @ Wk2 + bk2); writes duplicated pairs ----------------
__global__ __launch_bounds__(256) void k1a_wsoftmax(const float* __restrict__ x) {
    __shared__ float As[16][128];
    __shared__ u64   Bs2[16][32];
    __shared__ float sC[128][65];
    __shared__ float rmax[128], rinv[128];

    int tid = threadIdx.x;
    int tx = tid & 15;
    int ty = tid >> 4;
    int rowBase = blockIdx.x * 128;

    u64 acc2[8][2];
    #pragma unroll
    for (int i = 0; i < 8; i++) { acc2[i][0] = 0ull; acc2[i][1] = 0ull; }

    for (int kb = 0; kb < IND; kb += 16) {
        #pragma unroll
        for (int it = 0; it < 2; it++) {
            int f4 = tid + it * 256;
            int row = f4 >> 2, kk4 = f4 & 3;
            float4 v = *(const float4*)(x + (size_t)(rowBase + row) * IND + kb + kk4 * 4);
            As[kk4*4+0][row] = v.x; As[kk4*4+1][row] = v.y;
            As[kk4*4+2][row] = v.z; As[kk4*4+3][row] = v.w;
        }
        {
            int k = tid >> 4, n4 = tid & 15;
            float4 v = *(const float4*)(g_Wk2 + (size_t)(kb + k) * MM + n4 * 4);
            Bs2[k][n4*2+0] = pk2(v.x, v.y);
            Bs2[k][n4*2+1] = pk2(v.z, v.w);
        }
        __syncthreads();
        #pragma unroll
        for (int k = 0; k < 16; k++) {
            u64 rb0 = Bs2[k][tx];
            u64 rb1 = Bs2[k][tx + 16];
            #pragma unroll
            for (int i = 0; i < 8; i++) {
                float a = As[k][ty*8 + i];
                u64 a2 = pk2(a, a);
                acc2[i][0] = fma2(a2, rb0, acc2[i][0]);
                acc2[i][1] = fma2(a2, rb1, acc2[i][1]);
            }
        }
        __syncthreads();
    }
    float acc[8][4];
    float b0 = g_bk2[2*tx], b1 = g_bk2[2*tx+1], b2 = g_bk2[2*tx+32], b3 = g_bk2[2*tx+33];
    #pragma unroll
    for (int i = 0; i < 8; i++) {
        float lo, hi;
        upk2(lo, hi, acc2[i][0]);
        acc[i][0] = lo + b0; acc[i][1] = hi + b1;
        upk2(lo, hi, acc2[i][1]);
        acc[i][2] = lo + b2; acc[i][3] = hi + b3;
        int row = ty*8 + i;
        sC[row][2*tx]    = acc[i][0];
        sC[row][2*tx+1]  = acc[i][1];
        sC[row][2*tx+32] = acc[i][2];
        sC[row][2*tx+33] = acc[i][3];
    }
    __syncthreads();
    {
        int row = tid >> 1, h = tid & 1;
        float mx = -1e30f;
        #pragma unroll 8
        for (int i = 0; i < 32; i++) mx = fmaxf(mx, sC[row][h*32 + i]);
        mx = fmaxf(mx, __shfl_xor_sync(0xffffffffu, mx, 1));
        float s = 0.f;
        #pragma unroll 8
        for (int i = 0; i < 32; i++) s += expf(sC[row][h*32 + i] - mx);
        s += __shfl_xor_sync(0xffffffffu, s, 1);
        if (!h) { rmax[row] = mx; rinv[row] = 1.f / s; }
    }
    __syncthreads();
    #pragma unroll
    for (int i = 0; i < 8; i++) {
        int row = ty*8 + i;
        float m = rmax[row], inv = rinv[row];
        float* wd = g_wd + (size_t)(rowBase + row) * (2*MM);
        float w0 = expf(acc[i][0]-m)*inv;
        float w1 = expf(acc[i][1]-m)*inv;
        float w2 = expf(acc[i][2]-m)*inv;
        float w3 = expf(acc[i][3]-m)*inv;
        float4 p0; p0.x = w0; p0.y = w0; p0.z = w1; p0.w = w1;
        float4 p1; p1.x = w2; p1.y = w2; p1.z = w3; p1.w = w3;
        *(float4*)(wd + 4*tx)      = p0;   // m = 2tx, 2tx+1 duplicated
        *(float4*)(wd + 4*tx + 64) = p1;   // m = 2tx+32, 2tx+33 duplicated
    }
}

// ---------------- K1b: v = x @ Ww + bw ; stores interleaved {-sigmoid pair, tanh pair} ----------------
// g_ea layout per row: for d-pair p (=d/2, 0..63): [4p]=-sig(v_{2p}), [4p+1]=-sig(v_{2p+1}),
//                      [4p+2]=tanh(v_{2p}), [4p+3]=tanh(v_{2p+1})
__global__ __launch_bounds__(256) void k1b_ea(const float* __restrict__ x,
                                              const float* __restrict__ Ww,
                                              const float* __restrict__ bw) {
    __shared__ float As[16][128];
    __shared__ u64   Bs2[16][64];
    int tid = threadIdx.x;
    int tx = tid & 15;
    int ty = tid >> 4;
    int rowBase = blockIdx.x * 128;

    u64 acc2[8][4];
    #pragma unroll
    for (int i = 0; i < 8; i++)
        #pragma unroll
        for (int j = 0; j < 4; j++) acc2[i][j] = 0ull;

    for (int kb = 0; kb < IND; kb += 16) {
        #pragma unroll
        for (int it = 0; it < 2; it++) {
            int f4 = tid + it * 256;
            int row = f4 >> 2, kk4 = f4 & 3;
            float4 v = *(const float4*)(x + (size_t)(rowBase + row) * IND + kb + kk4 * 4);
            As[kk4*4+0][row] = v.x; As[kk4*4+1][row] = v.y;
            As[kk4*4+2][row] = v.z; As[kk4*4+3][row] = v.w;
        }
        #pragma unroll
        for (int it = 0; it < 2; it++) {
            int f4 = tid + it * 256;
            int k = f4 >> 5, n4 = f4 & 31;
            float4 v = *(const float4*)(Ww + (size_t)(kb + k) * DD + n4 * 4);
            Bs2[k][n4*2+0] = pk2(v.x, v.y);
            Bs2[k][n4*2+1] = pk2(v.z, v.w);
        }
        __syncthreads();
        #pragma unroll
        for (int k = 0; k < 16; k++) {
            u64 rb[4];
            #pragma unroll
            for (int j = 0; j < 4; j++) rb[j] = Bs2[k][tx + 16*j];
            #pragma unroll
            for (int i = 0; i < 8; i++) {
                float a = As[k][ty*8 + i];
                u64 a2 = pk2(a, a);
                #pragma unroll
                for (int j = 0; j < 4; j++) acc2[i][j] = fma2(a2, rb[j], acc2[i][j]);
            }
        }
        __syncthreads();
    }
    float blo[4], bhi[4];
    #pragma unroll
    for (int j = 0; j < 4; j++) {
        int c = 2*(tx + 16*j);
        blo[j] = bw[c]; bhi[j] = bw[c+1];
    }
    #pragma unroll
    for (int i = 0; i < 8; i++) {
        size_t row = (size_t)(rowBase + ty*8 + i);
        #pragma unroll
        for (int j = 0; j < 4; j++) {
            float lo, hi;
            upk2(lo, hi, acc2[i][j]);
            float v0 = lo + blo[j], v1 = hi + bhi[j];
            int p = tx + 16*j;               // d-pair index
            float4 eav;
            eav.x = -1.f/(1.f+expf(-v0));
            eav.y = -1.f/(1.f+expf(-v1));
            eav.z = tanhf(v0);
            eav.w = tanhf(v1);
            *(float4*)(g_ea + row*(2*DD) + 4*p) = eav;
        }
    }
}

// ---------------- K2: scan, 512 thr, deferred packed r-reduction (R4 winner + ea interleave) ----------------
// CTA = batch. 16 warps; warp owns d [warp*8, warp*8+8).
// lane: dp = lane&3 -> d-pair (d0 = warp*8 + dp*2); mq = lane>>2 -> m in [mq*8, mq*8+8)
__global__ __launch_bounds__(512) void k2_scan(const float* __restrict__ mv0) {
    int b = blockIdx.x;
    int warp = threadIdx.x >> 5, lane = threadIdx.x & 31;
    int dp = lane & 3, mq = lane >> 2;
    int d0 = warp * 8 + dp * 2;
    int m0 = mq * 8;

    const float* wdp = g_wd + (size_t)b * Ss * (2*MM) + 2*m0;
    const float* eap = g_ea + (size_t)b * Ss * (2*DD) + 2*d0;   // 4*(d0/2)
    float*       rp  = g_r  + (size_t)b * Ss * DD + d0;

    u64 Mv[8];
    #pragma unroll
    for (int j = 0; j < 8; j++)
        Mv[j] = *(const u64*)(mv0 + (size_t)(m0 + j) * DD + d0);

    // wb[s][q]: 16B = 2 duplicated w-pairs (m0+2q, m0+2q+1)
    longlong2 wb[2][4];
    longlong2 eav[2];   // .x = packed (-e pair), .y = packed (a pair)

#define FETCH(T, S) do { \
        const longlong2* wt = (const longlong2*)(wdp + (size_t)(T) * (2*MM)); \
        wb[S][0] = wt[0]; wb[S][1] = wt[1]; wb[S][2] = wt[2]; wb[S][3] = wt[3]; \
        eav[S] = *(const longlong2*)(eap + (size_t)(T) * (2*DD)); \
    } while (0)

    FETCH(0, 0);
    FETCH(1, 1);

    u64 rprev = 0ull;

    for (int t = 0; t < Ss; t += 2) {
        #pragma unroll
        for (int s = 0; s < 2; s++) {
            u64 en2 = (u64)eav[s].x;     // already negated sigmoid
            u64 a2c = (u64)eav[s].y;
            u64 wl0 = (u64)wb[s][0].x, wl1 = (u64)wb[s][0].y;
            u64 wl2 = (u64)wb[s][1].x, wl3 = (u64)wb[s][1].y;
            u64 wl4 = (u64)wb[s][2].x, wl5 = (u64)wb[s][2].y;
            u64 wl6 = (u64)wb[s][3].x, wl7 = (u64)wb[s][3].y;
            if (t + s + 2 < Ss) FETCH(t + s + 2, s);

            u64 r0, r1;
            {
                u64 t0 = mul2(wl0, Mv[0]); r0 = t0;
                Mv[0] = fma2(t0, en2, Mv[0]); Mv[0] = fma2(wl0, a2c, Mv[0]);
                u64 t1 = mul2(wl1, Mv[1]); r1 = t1;
                Mv[1] = fma2(t1, en2, Mv[1]); Mv[1] = fma2(wl1, a2c, Mv[1]);
                u64 t2 = mul2(wl2, Mv[2]); r0 = add2(r0, t2);
                Mv[2] = fma2(t2, en2, Mv[2]); Mv[2] = fma2(wl2, a2c, Mv[2]);
                u64 t3 = mul2(wl3, Mv[3]); r1 = add2(r1, t3);
                Mv[3] = fma2(t3, en2, Mv[3]); Mv[3] = fma2(wl3, a2c, Mv[3]);
                u64 t4 = mul2(wl4, Mv[4]); r0 = add2(r0, t4);
                Mv[4] = fma2(t4, en2, Mv[4]); Mv[4] = fma2(wl4, a2c, Mv[4]);
                u64 t5 = mul2(wl5, Mv[5]); r1 = add2(r1, t5);
                Mv[5] = fma2(t5, en2, Mv[5]); Mv[5] = fma2(wl5, a2c, Mv[5]);
                u64 t6 = mul2(wl6, Mv[6]); r0 = add2(r0, t6);
                Mv[6] = fma2(t6, en2, Mv[6]); Mv[6] = fma2(wl6, a2c, Mv[6]);
                u64 t7 = mul2(wl7, Mv[7]); r1 = add2(r1, t7);
                Mv[7] = fma2(t7, en2, Mv[7]); Mv[7] = fma2(wl7, a2c, Mv[7]);
            }
            // finalize PREVIOUS step's r (shfl latency off the critical path)
            {
                u64 p = rprev;
                p = add2(p, __shfl_xor_sync(0xffffffffu, p, 4));
                p = add2(p, __shfl_xor_sync(0xffffffffu, p, 8));
                p = add2(p, __shfl_xor_sync(0xffffffffu, p, 16));
                if ((t + s) > 0 && mq == 0)
                    *(u64*)(rp + (size_t)(t + s - 1) * DD) = p;
            }
            rprev = add2(r0, r1);
        }
    }
    // tail: finalize last step
    {
        u64 p = rprev;
        p = add2(p, __shfl_xor_sync(0xffffffffu, p, 4));
        p = add2(p, __shfl_xor_sync(0xffffffffu, p, 8));
        p = add2(p, __shfl_xor_sync(0xffffffffu, p, 16));
        if (mq == 0)
            *(u64*)(rp + (size_t)(Ss - 1) * DD) = p;
    }
#undef FETCH
}

// ---------------- K3: y = sigmoid(r @ Wp + bp) ----------------
__global__ __launch_bounds__(256) void k3_out(const float* __restrict__ Wp,
                                              const float* __restrict__ bp,
                                              float* __restrict__ out) {
    __shared__ float As[16][128];
    __shared__ u64   Bs2[16][64];
    int tid = threadIdx.x;
    int tx = tid & 15;
    int ty = tid >> 4;
    int rowBase = blockIdx.x * 128;

    u64 acc2[8][4];
    #pragma unroll
    for (int i = 0; i < 8; i++)
        #pragma unroll
        for (int j = 0; j < 4; j++) acc2[i][j] = 0ull;

    for (int kb = 0; kb < DD; kb += 16) {
        #pragma unroll
        for (int it = 0; it < 2; it++) {
            int f4 = tid + it * 256;
            int row = f4 >> 2, kk4 = f4 & 3;
            float4 v = *(const float4*)(g_r + (size_t)(rowBase + row) * DD + kb + kk4 * 4);
            As[kk4*4+0][row] = v.x; As[kk4*4+1][row] = v.y;
            As[kk4*4+2][row] = v.z; As[kk4*4+3][row] = v.w;
        }
        #pragma unroll
        for (int it = 0; it < 2; it++) {
            int f4 = tid + it * 256;
            int k = f4 >> 5, n4 = f4 & 31;
            float4 v = *(const float4*)(Wp + (size_t)(kb + k) * OUTD + n4 * 4);
            Bs2[k][n4*2+0] = pk2(v.x, v.y);
            Bs2[k][n4*2+1] = pk2(v.z, v.w);
        }
        __syncthreads();
        #pragma unroll
        for (int k = 0; k < 16; k++) {
            u64 rb[4];
            #pragma unroll
            for (int j = 0; j < 4; j++) rb[j] = Bs2[k][tx + 16*j];
            #pragma unroll
            for (int i = 0; i < 8; i++) {
                float a = As[k][ty*8 + i];
                u64 a2 = pk2(a, a);
                #pragma unroll
                for (int j = 0; j < 4; j++) acc2[i][j] = fma2(a2, rb[j], acc2[i][j]);
            }
        }
        __syncthreads();
    }
    float blo[4], bhi[4];
    #pragma unroll
    for (int j = 0; j < 4; j++) {
        int c = 2*(tx + 16*j);
        blo[j] = bp[c]; bhi[j] = bp[c+1];
    }
    #pragma unroll
    for (int i = 0; i < 8; i++) {
        size_t row = (size_t)(rowBase + ty*8 + i);
        #pragma unroll
        for (int j = 0; j < 4; j++) {
            float lo, hi;
            upk2(lo, hi, acc2[i][j]);
            float v0 = lo + blo[j], v1 = hi + bhi[j];
            int c = 2*(tx + 16*j);
            *(u64*)(out + row*OUTD + c) = pk2(1.f/(1.f+expf(-v0)), 1.f/(1.f+expf(-v1)));
        }
    }
}

// ---------------- launch ----------------
extern "C" void kernel_launch(void* const* d_in, const int* in_sizes, int n_in,
                              void* d_out, int out_size) {
    const float* x   = (const float*)d_in[0];
    const float* Mk  = (const float*)d_in[1];
    const float* Mv0 = (const float*)d_in[2];
    const float* Wr  = (const float*)d_in[3];
    const float* br  = (const float*)d_in[4];
    const float* Ww  = (const float*)d_in[5];
    const float* bw  = (const float*)d_in[6];
    const float* Wp  = (const float*)d_in[7];
    const float* bp  = (const float*)d_in[8];
    float* out = (float*)d_out;

    k0_fold<<<65, 256>>>(Wr, br, Mk);
    k1a_wsoftmax<<<ROWS/128, 256>>>(x);
    k1b_ea<<<ROWS/128, 256>>>(x, Ww, bw);
    k2_scan<<<Bb, 512>>>(Mv0);
    k3_out<<<ROWS/128, 256>>>(Wp, bp, out);
}

// round 9
// speedup vs baseline: 1.5290x; 1.0079x over previous
#include <cuda_runtime.h>
#include <math.h>

#define Bb   128
#define Ss   1024
#define IND  256
#define MM   64
#define DD   128
#define OUTD 128
#define ROWS (Bb*Ss)   // 131072

typedef unsigned long long u64;

__device__ __forceinline__ u64 pk2(float lo, float hi) {
    u64 r; asm("mov.b64 %0,{%1,%2};" : "=l"(r) : "f"(lo), "f"(hi)); return r;
}
__device__ __forceinline__ void upk2(float& lo, float& hi, u64 v) {
    asm("mov.b64 {%0,%1},%2;" : "=f"(lo), "=f"(hi) : "l"(v));
}
__device__ __forceinline__ u64 fma2(u64 a, u64 b, u64 c) {
    u64 d; asm("fma.rn.f32x2 %0,%1,%2,%3;" : "=l"(d) : "l"(a), "l"(b), "l"(c)); return d;
}
__device__ __forceinline__ u64 mul2(u64 a, u64 b) {
    u64 d; asm("mul.rn.f32x2 %0,%1,%2;" : "=l"(d) : "l"(a), "l"(b)); return d;
}
__device__ __forceinline__ u64 add2(u64 a, u64 b) {
    u64 d; asm("add.rn.f32x2 %0,%1,%2;" : "=l"(d) : "l"(a), "l"(b)); return d;
}

// ---------------- scratch ----------------
__device__ __align__(16) float g_Wk2[IND*MM];
__device__ __align__(16) float g_bk2[MM];
// g_wd row layout (128 floats): q-major blocks. dup-pair for m = mq*8 + 2q + h
// lives at float offset q*32 + mq*4 + 2h  (q=0..3, mq=0..7, h=0..1)
__device__ __align__(16) float g_wd[(size_t)ROWS*2*MM];   // 67MB
__device__ __align__(16) float g_ea[(size_t)ROWS*2*DD];   // interleaved {-sig pair, tanh pair} 134MB
__device__ __align__(16) float g_r[(size_t)ROWS*DD];      // read vectors 67MB

// ---------------- K0 ----------------
__global__ void k0_fold(const float* __restrict__ Wr, const float* __restrict__ br,
                        const float* __restrict__ Mk) {
    int gid = blockIdx.x * 256 + threadIdx.x;
    if (gid < IND*MM) {
        int i = gid >> 6, m = gid & 63;
        const float* wr = Wr + (size_t)i * DD;
        const float* mk = Mk + (size_t)m * DD;
        float s = 0.f;
        #pragma unroll 8
        for (int d = 0; d < DD; d++) s = fmaf(wr[d], mk[d], s);
        g_Wk2[i*MM + m] = s;
    } else if (gid < IND*MM + MM) {
        int m = gid - IND*MM;
        const float* mk = Mk + (size_t)m * DD;
        float s = 0.f;
        #pragma unroll 8
        for (int d = 0; d < DD; d++) s = fmaf(br[d], mk[d], s);
        g_bk2[m] = s;
    }
}

// ---------------- K1a: w = softmax(x @ Wk2 + bk2); writes duplicated pairs, q-major ----------------
__global__ __launch_bounds__(256) void k1a_wsoftmax(const float* __restrict__ x) {
    __shared__ float As[16][128];
    __shared__ u64   Bs2[16][32];
    __shared__ float sC[128][65];
    __shared__ float rmax[128], rinv[128];

    int tid = threadIdx.x;
    int tx = tid & 15;
    int ty = tid >> 4;
    int rowBase = blockIdx.x * 128;

    u64 acc2[8][2];
    #pragma unroll
    for (int i = 0; i < 8; i++) { acc2[i][0] = 0ull; acc2[i][1] = 0ull; }

    for (int kb = 0; kb < IND; kb += 16) {
        #pragma unroll
        for (int it = 0; it < 2; it++) {
            int f4 = tid + it * 256;
            int row = f4 >> 2, kk4 = f4 & 3;
            float4 v = *(const float4*)(x + (size_t)(rowBase + row) * IND + kb + kk4 * 4);
            As[kk4*4+0][row] = v.x; As[kk4*4+1][row] = v.y;
            As[kk4*4+2][row] = v.z; As[kk4*4+3][row] = v.w;
        }
        {
            int k = tid >> 4, n4 = tid & 15;
            float4 v = *(const float4*)(g_Wk2 + (size_t)(kb + k) * MM + n4 * 4);
            Bs2[k][n4*2+0] = pk2(v.x, v.y);
            Bs2[k][n4*2+1] = pk2(v.z, v.w);
        }
        __syncthreads();
        #pragma unroll
        for (int k = 0; k < 16; k++) {
            u64 rb0 = Bs2[k][tx];
            u64 rb1 = Bs2[k][tx + 16];
            #pragma unroll
            for (int i = 0; i < 8; i++) {
                float a = As[k][ty*8 + i];
                u64 a2 = pk2(a, a);
                acc2[i][0] = fma2(a2, rb0, acc2[i][0]);
                acc2[i][1] = fma2(a2, rb1, acc2[i][1]);
            }
        }
        __syncthreads();
    }
    float acc[8][4];
    float b0 = g_bk2[2*tx], b1 = g_bk2[2*tx+1], b2 = g_bk2[2*tx+32], b3 = g_bk2[2*tx+33];
    #pragma unroll
    for (int i = 0; i < 8; i++) {
        float lo, hi;
        upk2(lo, hi, acc2[i][0]);
        acc[i][0] = lo + b0; acc[i][1] = hi + b1;
        upk2(lo, hi, acc2[i][1]);
        acc[i][2] = lo + b2; acc[i][3] = hi + b3;
        int row = ty*8 + i;
        sC[row][2*tx]    = acc[i][0];
        sC[row][2*tx+1]  = acc[i][1];
        sC[row][2*tx+32] = acc[i][2];
        sC[row][2*tx+33] = acc[i][3];
    }
    __syncthreads();
    {
        int row = tid >> 1, h = tid & 1;
        float mx = -1e30f;
        #pragma unroll 8
        for (int i = 0; i < 32; i++) mx = fmaxf(mx, sC[row][h*32 + i]);
        mx = fmaxf(mx, __shfl_xor_sync(0xffffffffu, mx, 1));
        float s = 0.f;
        #pragma unroll 8
        for (int i = 0; i < 32; i++) s += expf(sC[row][h*32 + i] - mx);
        s += __shfl_xor_sync(0xffffffffu, s, 1);
        if (!h) { rmax[row] = mx; rinv[row] = 1.f / s; }
    }
    __syncthreads();
    // q-major duplicated store: m = 2tx   -> q = tx&3, mq = tx>>2   (offset q*32 + mq*4)
    //                           m = 2tx+32 -> same q, mq+4          (offset +16)
    {
        int q0  = tx & 3;
        int mq0 = tx >> 2;
        int off = q0*32 + mq0*4;
        #pragma unroll
        for (int i = 0; i < 8; i++) {
            int row = ty*8 + i;
            float m = rmax[row], inv = rinv[row];
            float* wd = g_wd + (size_t)(rowBase + row) * (2*MM);
            float w0 = expf(acc[i][0]-m)*inv;
            float w1 = expf(acc[i][1]-m)*inv;
            float w2 = expf(acc[i][2]-m)*inv;
            float w3 = expf(acc[i][3]-m)*inv;
            float4 p0; p0.x = w0; p0.y = w0; p0.z = w1; p0.w = w1;
            float4 p1; p1.x = w2; p1.y = w2; p1.z = w3; p1.w = w3;
            *(float4*)(wd + off)      = p0;   // m = 2tx, 2tx+1
            *(float4*)(wd + off + 16) = p1;   // m = 2tx+32, 2tx+33
        }
    }
}

// ---------------- K1b: v = x @ Ww + bw ; stores interleaved {-sigmoid pair, tanh pair} ----------------
__global__ __launch_bounds__(256) void k1b_ea(const float* __restrict__ x,
                                              const float* __restrict__ Ww,
                                              const float* __restrict__ bw) {
    __shared__ float As[16][128];
    __shared__ u64   Bs2[16][64];
    int tid = threadIdx.x;
    int tx = tid & 15;
    int ty = tid >> 4;
    int rowBase = blockIdx.x * 128;

    u64 acc2[8][4];
    #pragma unroll
    for (int i = 0; i < 8; i++)
        #pragma unroll
        for (int j = 0; j < 4; j++) acc2[i][j] = 0ull;

    for (int kb = 0; kb < IND; kb += 16) {
        #pragma unroll
        for (int it = 0; it < 2; it++) {
            int f4 = tid + it * 256;
            int row = f4 >> 2, kk4 = f4 & 3;
            float4 v = *(const float4*)(x + (size_t)(rowBase + row) * IND + kb + kk4 * 4);
            As[kk4*4+0][row] = v.x; As[kk4*4+1][row] = v.y;
            As[kk4*4+2][row] = v.z; As[kk4*4+3][row] = v.w;
        }
        #pragma unroll
        for (int it = 0; it < 2; it++) {
            int f4 = tid + it * 256;
            int k = f4 >> 5, n4 = f4 & 31;
            float4 v = *(const float4*)(Ww + (size_t)(kb + k) * DD + n4 * 4);
            Bs2[k][n4*2+0] = pk2(v.x, v.y);
            Bs2[k][n4*2+1] = pk2(v.z, v.w);
        }
        __syncthreads();
        #pragma unroll
        for (int k = 0; k < 16; k++) {
            u64 rb[4];
            #pragma unroll
            for (int j = 0; j < 4; j++) rb[j] = Bs2[k][tx + 16*j];
            #pragma unroll
            for (int i = 0; i < 8; i++) {
                float a = As[k][ty*8 + i];
                u64 a2 = pk2(a, a);
                #pragma unroll
                for (int j = 0; j < 4; j++) acc2[i][j] = fma2(a2, rb[j], acc2[i][j]);
            }
        }
        __syncthreads();
    }
    float blo[4], bhi[4];
    #pragma unroll
    for (int j = 0; j < 4; j++) {
        int c = 2*(tx + 16*j);
        blo[j] = bw[c]; bhi[j] = bw[c+1];
    }
    #pragma unroll
    for (int i = 0; i < 8; i++) {
        size_t row = (size_t)(rowBase + ty*8 + i);
        #pragma unroll
        for (int j = 0; j < 4; j++) {
            float lo, hi;
            upk2(lo, hi, acc2[i][j]);
            float v0 = lo + blo[j], v1 = hi + bhi[j];
            int p = tx + 16*j;               // d-pair index
            float4 eav;
            eav.x = -1.f/(1.f+expf(-v0));
            eav.y = -1.f/(1.f+expf(-v1));
            eav.z = tanhf(v0);
            eav.w = tanhf(v1);
            *(float4*)(g_ea + row*(2*DD) + 4*p) = eav;
        }
    }
}

// ---------------- K2: scan, 512 thr, q-major single-line w loads ----------------
// CTA = batch. 16 warps; warp owns d [warp*8, warp*8+8).
// lane: dp = lane&3 -> d-pair (d0 = warp*8 + dp*2); mq = lane>>2 -> m in [mq*8, mq*8+8)
__global__ __launch_bounds__(512) void k2_scan(const float* __restrict__ mv0) {
    int b = blockIdx.x;
    int warp = threadIdx.x >> 5, lane = threadIdx.x & 31;
    int dp = lane & 3, mq = lane >> 2;
    int d0 = warp * 8 + dp * 2;
    int m0 = mq * 8;

    // q-major w: lane reads 16B at  row_base + q*128B + mq*16B
    const float* wdp = g_wd + (size_t)b * Ss * (2*MM) + mq * 4;
    const float* eap = g_ea + (size_t)b * Ss * (2*DD) + 2*d0;
    float*       rp  = g_r  + (size_t)b * Ss * DD + d0;

    u64 Mv[8];
    #pragma unroll
    for (int j = 0; j < 8; j++)
        Mv[j] = *(const u64*)(mv0 + (size_t)(m0 + j) * DD + d0);

    // wb[s][q]: 16B = dup pairs for m = m0+2q (.x), m0+2q+1 (.y)
    longlong2 wb[2][4];
    longlong2 eav[2];   // .x = packed (-e pair), .y = packed (a pair)

#define FETCH(T, S) do { \
        const float* wt = wdp + (size_t)(T) * (2*MM); \
        wb[S][0] = *(const longlong2*)(wt +  0); \
        wb[S][1] = *(const longlong2*)(wt + 32); \
        wb[S][2] = *(const longlong2*)(wt + 64); \
        wb[S][3] = *(const longlong2*)(wt + 96); \
        eav[S] = *(const longlong2*)(eap + (size_t)(T) * (2*DD)); \
    } while (0)

    FETCH(0, 0);
    FETCH(1, 1);

    u64 rprev = 0ull;

    for (int t = 0; t < Ss; t += 2) {
        #pragma unroll
        for (int s = 0; s < 2; s++) {
            u64 en2 = (u64)eav[s].x;     // already negated sigmoid
            u64 a2c = (u64)eav[s].y;
            u64 wl0 = (u64)wb[s][0].x, wl1 = (u64)wb[s][0].y;
            u64 wl2 = (u64)wb[s][1].x, wl3 = (u64)wb[s][1].y;
            u64 wl4 = (u64)wb[s][2].x, wl5 = (u64)wb[s][2].y;
            u64 wl6 = (u64)wb[s][3].x, wl7 = (u64)wb[s][3].y;
            if (t + s + 2 < Ss) FETCH(t + s + 2, s);

            u64 r0, r1;
            {
                u64 t0 = mul2(wl0, Mv[0]); r0 = t0;
                Mv[0] = fma2(t0, en2, Mv[0]); Mv[0] = fma2(wl0, a2c, Mv[0]);
                u64 t1 = mul2(wl1, Mv[1]); r1 = t1;
                Mv[1] = fma2(t1, en2, Mv[1]); Mv[1] = fma2(wl1, a2c, Mv[1]);
                u64 t2 = mul2(wl2, Mv[2]); r0 = add2(r0, t2);
                Mv[2] = fma2(t2, en2, Mv[2]); Mv[2] = fma2(wl2, a2c, Mv[2]);
                u64 t3 = mul2(wl3, Mv[3]); r1 = add2(r1, t3);
                Mv[3] = fma2(t3, en2, Mv[3]); Mv[3] = fma2(wl3, a2c, Mv[3]);
                u64 t4 = mul2(wl4, Mv[4]); r0 = add2(r0, t4);
                Mv[4] = fma2(t4, en2, Mv[4]); Mv[4] = fma2(wl4, a2c, Mv[4]);
                u64 t5 = mul2(wl5, Mv[5]); r1 = add2(r1, t5);
                Mv[5] = fma2(t5, en2, Mv[5]); Mv[5] = fma2(wl5, a2c, Mv[5]);
                u64 t6 = mul2(wl6, Mv[6]); r0 = add2(r0, t6);
                Mv[6] = fma2(t6, en2, Mv[6]); Mv[6] = fma2(wl6, a2c, Mv[6]);
                u64 t7 = mul2(wl7, Mv[7]); r1 = add2(r1, t7);
                Mv[7] = fma2(t7, en2, Mv[7]); Mv[7] = fma2(wl7, a2c, Mv[7]);
            }
            // finalize PREVIOUS step's r (shfl latency off the critical path)
            {
                u64 p = rprev;
                p = add2(p, __shfl_xor_sync(0xffffffffu, p, 4));
                p = add2(p, __shfl_xor_sync(0xffffffffu, p, 8));
                p = add2(p, __shfl_xor_sync(0xffffffffu, p, 16));
                if ((t + s) > 0 && mq == 0)
                    *(u64*)(rp + (size_t)(t + s - 1) * DD) = p;
            }
            rprev = add2(r0, r1);
        }
    }
    // tail: finalize last step
    {
        u64 p = rprev;
        p = add2(p, __shfl_xor_sync(0xffffffffu, p, 4));
        p = add2(p, __shfl_xor_sync(0xffffffffu, p, 8));
        p = add2(p, __shfl_xor_sync(0xffffffffu, p, 16));
        if (mq == 0)
            *(u64*)(rp + (size_t)(Ss - 1) * DD) = p;
    }
#undef FETCH
}

// ---------------- K3: y = sigmoid(r @ Wp + bp) ----------------
__global__ __launch_bounds__(256) void k3_out(const float* __restrict__ Wp,
                                              const float* __restrict__ bp,
                                              float* __restrict__ out) {
    __shared__ float As[16][128];
    __shared__ u64   Bs2[16][64];
    int tid = threadIdx.x;
    int tx = tid & 15;
    int ty = tid >> 4;
    int rowBase = blockIdx.x * 128;

    u64 acc2[8][4];
    #pragma unroll
    for (int i = 0; i < 8; i++)
        #pragma unroll
        for (int j = 0; j < 4; j++) acc2[i][j] = 0ull;

    for (int kb = 0; kb < DD; kb += 16) {
        #pragma unroll
        for (int it = 0; it < 2; it++) {
            int f4 = tid + it * 256;
            int row = f4 >> 2, kk4 = f4 & 3;
            float4 v = *(const float4*)(g_r + (size_t)(rowBase + row) * DD + kb + kk4 * 4);
            As[kk4*4+0][row] = v.x; As[kk4*4+1][row] = v.y;
            As[kk4*4+2][row] = v.z; As[kk4*4+3][row] = v.w;
        }
        #pragma unroll
        for (int it = 0; it < 2; it++) {
            int f4 = tid + it * 256;
            int k = f4 >> 5, n4 = f4 & 31;
            float4 v = *(const float4*)(Wp + (size_t)(kb + k) * OUTD + n4 * 4);
            Bs2[k][n4*2+0] = pk2(v.x, v.y);
            Bs2[k][n4*2+1] = pk2(v.z, v.w);
        }
        __syncthreads();
        #pragma unroll
        for (int k = 0; k < 16; k++) {
            u64 rb[4];
            #pragma unroll
            for (int j = 0; j < 4; j++) rb[j] = Bs2[k][tx + 16*j];
            #pragma unroll
            for (int i = 0; i < 8; i++) {
                float a = As[k][ty*8 + i];
                u64 a2 = pk2(a, a);
                #pragma unroll
                for (int j = 0; j < 4; j++) acc2[i][j] = fma2(a2, rb[j], acc2[i][j]);
            }
        }
        __syncthreads();
    }
    float blo[4], bhi[4];
    #pragma unroll
    for (int j = 0; j < 4; j++) {
        int c = 2*(tx + 16*j);
        blo[j] = bp[c]; bhi[j] = bp[c+1];
    }
    #pragma unroll
    for (int i = 0; i < 8; i++) {
        size_t row = (size_t)(rowBase + ty*8 + i);
        #pragma unroll
        for (int j = 0; j < 4; j++) {
            float lo, hi;
            upk2(lo, hi, acc2[i][j]);
            float v0 = lo + blo[j], v1 = hi + bhi[j];
            int c = 2*(tx + 16*j);
            *(u64*)(out + row*OUTD + c) = pk2(1.f/(1.f+expf(-v0)), 1.f/(1.f+expf(-v1)));
        }
    }
}

// ---------------- launch ----------------
extern "C" void kernel_launch(void* const* d_in, const int* in_sizes, int n_in,
                              void* d_out, int out_size) {
    const float* x   = (const float*)d_in[0];
    const float* Mk  = (const float*)d_in[1];
    const float* Mv0 = (const float*)d_in[2];
    const float* Wr  = (const float*)d_in[3];
    const float* br  = (const float*)d_in[4];
    const float* Ww  = (const float*)d_in[5];
    const float* bw  = (const float*)d_in[6];
    const float* Wp  = (const float*)d_in[7];
    const float* bp  = (const float*)d_in[8];
    float* out = (float*)d_out;

    k0_fold<<<65, 256>>>(Wr, br, Mk);
    k1a_wsoftmax<<<ROWS/128, 256>>>(x);
    k1b_ea<<<ROWS/128, 256>>>(x, Ww, bw);
    k2_scan<<<Bb, 512>>>(Mv0);
    k3_out<<<ROWS/128, 256>>>(Wp, bp, out);
}

// round 12
// speedup vs baseline: 1.8279x; 1.1955x over previous
#include <cuda_runtime.h>
#include <math.h>

#define Bb   128
#define Ss   1024
#define IND  256
#define MM   64
#define DD   128
#define OUTD 128
#define ROWS (Bb*Ss)   // 131072
#define SB   8         // scan steps staged per smem block
#define NBLK (Ss/SB)   // 128

typedef unsigned long long u64;

__device__ __forceinline__ u64 pk2(float lo, float hi) {
    u64 r; asm("mov.b64 %0,{%1,%2};" : "=l"(r) : "f"(lo), "f"(hi)); return r;
}
__device__ __forceinline__ void upk2(float& lo, float& hi, u64 v) {
    asm("mov.b64 {%0,%1},%2;" : "=f"(lo), "=f"(hi) : "l"(v));
}
__device__ __forceinline__ u64 fma2(u64 a, u64 b, u64 c) {
    u64 d; asm("fma.rn.f32x2 %0,%1,%2,%3;" : "=l"(d) : "l"(a), "l"(b), "l"(c)); return d;
}
__device__ __forceinline__ u64 mul2(u64 a, u64 b) {
    u64 d; asm("mul.rn.f32x2 %0,%1,%2;" : "=l"(d) : "l"(a), "l"(b)); return d;
}
__device__ __forceinline__ u64 add2(u64 a, u64 b) {
    u64 d; asm("add.rn.f32x2 %0,%1,%2;" : "=l"(d) : "l"(a), "l"(b)); return d;
}
__device__ __forceinline__ void cpa16(void* smem, const void* gmem) {
    unsigned s = (unsigned)__cvta_generic_to_shared(smem);
    asm volatile("cp.async.cg.shared.global [%0],[%1],16;\n" :: "r"(s), "l"(gmem) : "memory");
}
__device__ __forceinline__ void cpa_commit() {
    asm volatile("cp.async.commit_group;\n" ::: "memory");
}
template<int N> __device__ __forceinline__ void cpa_wait() {
    asm volatile("cp.async.wait_group %0;\n" :: "n"(N) : "memory");
}

// ---------------- scratch ----------------
__device__ __align__(16) float g_Wk2[IND*MM];
__device__ __align__(16) float g_bk2[MM];
// g_wd row layout (128 floats): q-major blocks. dup-pair for m = mq*8 + 2q + h
// lives at float offset q*32 + mq*4 + 2h  (q=0..3, mq=0..7, h=0..1)
__device__ __align__(16) float g_wd[(size_t)ROWS*2*MM];   // 67MB
__device__ __align__(16) float g_ea[(size_t)ROWS*2*DD];   // interleaved {-sig pair, tanh pair} 134MB
__device__ __align__(16) float g_r[(size_t)ROWS*DD];      // read vectors 67MB

// ---------------- K0 ----------------
__global__ void k0_fold(const float* __restrict__ Wr, const float* __restrict__ br,
                        const float* __restrict__ Mk) {
    int gid = blockIdx.x * 256 + threadIdx.x;
    if (gid < IND*MM) {
        int i = gid >> 6, m = gid & 63;
        const float* wr = Wr + (size_t)i * DD;
        const float* mk = Mk + (size_t)m * DD;
        float s = 0.f;
        #pragma unroll 8
        for (int d = 0; d < DD; d++) s = fmaf(wr[d], mk[d], s);
        g_Wk2[i*MM + m] = s;
    } else if (gid < IND*MM + MM) {
        int m = gid - IND*MM;
        const float* mk = Mk + (size_t)m * DD;
        float s = 0.f;
        #pragma unroll 8
        for (int d = 0; d < DD; d++) s = fmaf(br[d], mk[d], s);
        g_bk2[m] = s;
    }
}

// ---------------- K1a: w = softmax(x @ Wk2 + bk2); writes duplicated pairs, q-major ----------------
__global__ __launch_bounds__(256) void k1a_wsoftmax(const float* __restrict__ x) {
    __shared__ float As[16][128];
    __shared__ u64   Bs2[16][32];
    __shared__ float sC[128][65];
    __shared__ float rmax[128], rinv[128];

    int tid = threadIdx.x;
    int tx = tid & 15;
    int ty = tid >> 4;
    int rowBase = blockIdx.x * 128;

    u64 acc2[8][2];
    #pragma unroll
    for (int i = 0; i < 8; i++) { acc2[i][0] = 0ull; acc2[i][1] = 0ull; }

    for (int kb = 0; kb < IND; kb += 16) {
        #pragma unroll
        for (int it = 0; it < 2; it++) {
            int f4 = tid + it * 256;
            int row = f4 >> 2, kk4 = f4 & 3;
            float4 v = *(const float4*)(x + (size_t)(rowBase + row) * IND + kb + kk4 * 4);
            As[kk4*4+0][row] = v.x; As[kk4*4+1][row] = v.y;
            As[kk4*4+2][row] = v.z; As[kk4*4+3][row] = v.w;
        }
        {
            int k = tid >> 4, n4 = tid & 15;
            float4 v = *(const float4*)(g_Wk2 + (size_t)(kb + k) * MM + n4 * 4);
            Bs2[k][n4*2+0] = pk2(v.x, v.y);
            Bs2[k][n4*2+1] = pk2(v.z, v.w);
        }
        __syncthreads();
        #pragma unroll
        for (int k = 0; k < 16; k++) {
            u64 rb0 = Bs2[k][tx];
            u64 rb1 = Bs2[k][tx + 16];
            #pragma unroll
            for (int i = 0; i < 8; i++) {
                float a = As[k][ty*8 + i];
                u64 a2 = pk2(a, a);
                acc2[i][0] = fma2(a2, rb0, acc2[i][0]);
                acc2[i][1] = fma2(a2, rb1, acc2[i][1]);
            }
        }
        __syncthreads();
    }
    float acc[8][4];
    float b0 = g_bk2[2*tx], b1 = g_bk2[2*tx+1], b2 = g_bk2[2*tx+32], b3 = g_bk2[2*tx+33];
    #pragma unroll
    for (int i = 0; i < 8; i++) {
        float lo, hi;
        upk2(lo, hi, acc2[i][0]);
        acc[i][0] = lo + b0; acc[i][1] = hi + b1;
        upk2(lo, hi, acc2[i][1]);
        acc[i][2] = lo + b2; acc[i][3] = hi + b3;
        int row = ty*8 + i;
        sC[row][2*tx]    = acc[i][0];
        sC[row][2*tx+1]  = acc[i][1];
        sC[row][2*tx+32] = acc[i][2];
        sC[row][2*tx+33] = acc[i][3];
    }
    __syncthreads();
    {
        int row = tid >> 1, h = tid & 1;
        float mx = -1e30f;
        #pragma unroll 8
        for (int i = 0; i < 32; i++) mx = fmaxf(mx, sC[row][h*32 + i]);
        mx = fmaxf(mx, __shfl_xor_sync(0xffffffffu, mx, 1));
        float s = 0.f;
        #pragma unroll 8
        for (int i = 0; i < 32; i++) s += expf(sC[row][h*32 + i] - mx);
        s += __shfl_xor_sync(0xffffffffu, s, 1);
        if (!h) { rmax[row] = mx; rinv[row] = 1.f / s; }
    }
    __syncthreads();
    // q-major duplicated store
    {
        int q0  = tx & 3;
        int mq0 = tx >> 2;
        int off = q0*32 + mq0*4;
        #pragma unroll
        for (int i = 0; i < 8; i++) {
            int row = ty*8 + i;
            float m = rmax[row], inv = rinv[row];
            float* wd = g_wd + (size_t)(rowBase + row) * (2*MM);
            float w0 = expf(acc[i][0]-m)*inv;
            float w1 = expf(acc[i][1]-m)*inv;
            float w2 = expf(acc[i][2]-m)*inv;
            float w3 = expf(acc[i][3]-m)*inv;
            float4 p0; p0.x = w0; p0.y = w0; p0.z = w1; p0.w = w1;
            float4 p1; p1.x = w2; p1.y = w2; p1.z = w3; p1.w = w3;
            *(float4*)(wd + off)      = p0;   // m = 2tx, 2tx+1
            *(float4*)(wd + off + 16) = p1;   // m = 2tx+32, 2tx+33
        }
    }
}

// ---------------- K1b: v = x @ Ww + bw ; stores interleaved {-sigmoid pair, tanh pair} ----------------
__global__ __launch_bounds__(256) void k1b_ea(const float* __restrict__ x,
                                              const float* __restrict__ Ww,
                                              const float* __restrict__ bw) {
    __shared__ float As[16][128];
    __shared__ u64   Bs2[16][64];
    int tid = threadIdx.x;
    int tx = tid & 15;
    int ty = tid >> 4;
    int rowBase = blockIdx.x * 128;

    u64 acc2[8][4];
    #pragma unroll
    for (int i = 0; i < 8; i++)
        #pragma unroll
        for (int j = 0; j < 4; j++) acc2[i][j] = 0ull;

    for (int kb = 0; kb < IND; kb += 16) {
        #pragma unroll
        for (int it = 0; it < 2; it++) {
            int f4 = tid + it * 256;
            int row = f4 >> 2, kk4 = f4 & 3;
            float4 v = *(const float4*)(x + (size_t)(rowBase + row) * IND + kb + kk4 * 4);
            As[kk4*4+0][row] = v.x; As[kk4*4+1][row] = v.y;
            As[kk4*4+2][row] = v.z; As[kk4*4+3][row] = v.w;
        }
        #pragma unroll
        for (int it = 0; it < 2; it++) {
            int f4 = tid + it * 256;
            int k = f4 >> 5, n4 = f4 & 31;
            float4 v = *(const float4*)(Ww + (size_t)(kb + k) * DD + n4 * 4);
            Bs2[k][n4*2+0] = pk2(v.x, v.y);
            Bs2[k][n4*2+1] = pk2(v.z, v.w);
        }
        __syncthreads();
        #pragma unroll
        for (int k = 0; k < 16; k++) {
            u64 rb[4];
            #pragma unroll
            for (int j = 0; j < 4; j++) rb[j] = Bs2[k][tx + 16*j];
            #pragma unroll
            for (int i = 0; i < 8; i++) {
                float a = As[k][ty*8 + i];
                u64 a2 = pk2(a, a);
                #pragma unroll
                for (int j = 0; j < 4; j++) acc2[i][j] = fma2(a2, rb[j], acc2[i][j]);
            }
        }
        __syncthreads();
    }
    float blo[4], bhi[4];
    #pragma unroll
    for (int j = 0; j < 4; j++) {
        int c = 2*(tx + 16*j);
        blo[j] = bw[c]; bhi[j] = bw[c+1];
    }
    #pragma unroll
    for (int i = 0; i < 8; i++) {
        size_t row = (size_t)(rowBase + ty*8 + i);
        #pragma unroll
        for (int j = 0; j < 4; j++) {
            float lo, hi;
            upk2(lo, hi, acc2[i][j]);
            float v0 = lo + blo[j], v1 = hi + bhi[j];
            int p = tx + 16*j;               // d-pair index
            float4 eav;
            eav.x = -1.f/(1.f+expf(-v0));
            eav.y = -1.f/(1.f+expf(-v1));
            eav.z = tanhf(v0);
            eav.w = tanhf(v1);
            *(float4*)(g_ea + row*(2*DD) + 4*p) = eav;
        }
    }
}

// ---------------- K2: scan; coefficients staged via cp.async into smem, consumed by LDS broadcast ----------------
// CTA = batch. 16 warps; warp owns d [warp*8, warp*8+8).
// lane: dp = lane&3 -> d-pair (d0 = warp*8 + dp*2); mq = lane>>2 -> m in [mq*8, mq*8+8)
__global__ __launch_bounds__(512) void k2_scan(const float* __restrict__ mv0) {
    __shared__ __align__(16) float sw[2][SB*128];    // 2 x 4KB  (dup w, q-major per step row)
    __shared__ __align__(16) float sea[2][SB*256];   // 2 x 8KB  (interleaved ea per step row)

    int b = blockIdx.x;
    int tid = threadIdx.x;
    int warp = tid >> 5, lane = tid & 31;
    int dp = lane & 3, mq = lane >> 2;
    int d0 = warp * 8 + dp * 2;
    int m0 = mq * 8;

    const float* wsrc  = g_wd + (size_t)b * Ss * 128;   // rows contiguous, 512B each
    const float* easrc = g_ea + (size_t)b * Ss * 256;   // rows contiguous, 1KB each
    float*       rp    = g_r  + (size_t)b * Ss * DD + d0;

    u64 Mv[8];
    #pragma unroll
    for (int j = 0; j < 8; j++)
        Mv[j] = *(const u64*)(mv0 + (size_t)(m0 + j) * DD + d0);

    // stage block blk (SB steps) into buffer bf: w 4KB (256 f4), ea 8KB (512 f4)
#define STAGE(BLK, BF) do { \
        const float4* ws = (const float4*)(wsrc  + (size_t)(BLK) * SB * 128); \
        const float4* es = (const float4*)(easrc + (size_t)(BLK) * SB * 256); \
        float4* wdst = (float4*)sw[BF]; \
        float4* edst = (float4*)sea[BF]; \
        if (tid < 256) cpa16(&wdst[tid], &ws[tid]); \
        cpa16(&edst[tid], &es[tid]); \
    } while (0)

    STAGE(0, 0); cpa_commit();
    STAGE(1, 1); cpa_commit();

    u64 rprev = 0ull;

    for (int blk = 0; blk < NBLK; blk++) {
        int bf = blk & 1;
        cpa_wait<1>();
        __syncthreads();

        const float* wbase  = sw[bf]  + mq * 4;
        const float* eabase = sea[bf] + (warp * 4 + dp) * 4;

        #pragma unroll
        for (int s = 0; s < SB; s++) {
            int t = blk * SB + s;
            const float* wrow = wbase + s * 128;
            longlong2 q0 = *(const longlong2*)(wrow +  0);
            longlong2 q1 = *(const longlong2*)(wrow + 32);
            longlong2 q2 = *(const longlong2*)(wrow + 64);
            longlong2 q3 = *(const longlong2*)(wrow + 96);
            longlong2 ea = *(const longlong2*)(eabase + s * 256);

            u64 en2 = (u64)ea.x;       // already negated sigmoid
            u64 a2c = (u64)ea.y;
            u64 wl0 = (u64)q0.x, wl1 = (u64)q0.y;
            u64 wl2 = (u64)q1.x, wl3 = (u64)q1.y;
            u64 wl4 = (u64)q2.x, wl5 = (u64)q2.y;
            u64 wl6 = (u64)q3.x, wl7 = (u64)q3.y;

            u64 r0, r1;
            {
                u64 t0 = mul2(wl0, Mv[0]); r0 = t0;
                Mv[0] = fma2(t0, en2, Mv[0]); Mv[0] = fma2(wl0, a2c, Mv[0]);
                u64 t1 = mul2(wl1, Mv[1]); r1 = t1;
                Mv[1] = fma2(t1, en2, Mv[1]); Mv[1] = fma2(wl1, a2c, Mv[1]);
                u64 t2 = mul2(wl2, Mv[2]); r0 = add2(r0, t2);
                Mv[2] = fma2(t2, en2, Mv[2]); Mv[2] = fma2(wl2, a2c, Mv[2]);
                u64 t3 = mul2(wl3, Mv[3]); r1 = add2(r1, t3);
                Mv[3] = fma2(t3, en2, Mv[3]); Mv[3] = fma2(wl3, a2c, Mv[3]);
                u64 t4 = mul2(wl4, Mv[4]); r0 = add2(r0, t4);
                Mv[4] = fma2(t4, en2, Mv[4]); Mv[4] = fma2(wl4, a2c, Mv[4]);
                u64 t5 = mul2(wl5, Mv[5]); r1 = add2(r1, t5);
                Mv[5] = fma2(t5, en2, Mv[5]); Mv[5] = fma2(wl5, a2c, Mv[5]);
                u64 t6 = mul2(wl6, Mv[6]); r0 = add2(r0, t6);
                Mv[6] = fma2(t6, en2, Mv[6]); Mv[6] = fma2(wl6, a2c, Mv[6]);
                u64 t7 = mul2(wl7, Mv[7]); r1 = add2(r1, t7);
                Mv[7] = fma2(t7, en2, Mv[7]); Mv[7] = fma2(wl7, a2c, Mv[7]);
            }
            // finalize PREVIOUS step's r (shfl latency off the critical path)
            {
                u64 p = rprev;
                p = add2(p, __shfl_xor_sync(0xffffffffu, p, 4));
                p = add2(p, __shfl_xor_sync(0xffffffffu, p, 8));
                p = add2(p, __shfl_xor_sync(0xffffffffu, p, 16));
                if (t > 0 && mq == 0)
                    *(u64*)(rp + (size_t)(t - 1) * DD) = p;
            }
            rprev = add2(r0, r1);
        }

        __syncthreads();
        if (blk + 2 < NBLK) STAGE(blk + 2, bf);
        cpa_commit();
    }
    // tail: finalize last step
    {
        u64 p = rprev;
        p = add2(p, __shfl_xor_sync(0xffffffffu, p, 4));
        p = add2(p, __shfl_xor_sync(0xffffffffu, p, 8));
        p = add2(p, __shfl_xor_sync(0xffffffffu, p, 16));
        if (mq == 0)
            *(u64*)(rp + (size_t)(Ss - 1) * DD) = p;
    }
#undef STAGE
}

// ---------------- K3: y = sigmoid(r @ Wp + bp) ----------------
__global__ __launch_bounds__(256) void k3_out(const float* __restrict__ Wp,
                                              const float* __restrict__ bp,
                                              float* __restrict__ out) {
    __shared__ float As[16][128];
    __shared__ u64   Bs2[16][64];
    int tid = threadIdx.x;
    int tx = tid & 15;
    int ty = tid >> 4;
    int rowBase = blockIdx.x * 128;

    u64 acc2[8][4];
    #pragma unroll
    for (int i = 0; i < 8; i++)
        #pragma unroll
        for (int j = 0; j < 4; j++) acc2[i][j] = 0ull;

    for (int kb = 0; kb < DD; kb += 16) {
        #pragma unroll
        for (int it = 0; it < 2; it++) {
            int f4 = tid + it * 256;
            int row = f4 >> 2, kk4 = f4 & 3;
            float4 v = *(const float4*)(g_r + (size_t)(rowBase + row) * DD + kb + kk4 * 4);
            As[kk4*4+0][row] = v.x; As[kk4*4+1][row] = v.y;
            As[kk4*4+2][row] = v.z; As[kk4*4+3][row] = v.w;
        }
        #pragma unroll
        for (int it = 0; it < 2; it++) {
            int f4 = tid + it * 256;
            int k = f4 >> 5, n4 = f4 & 31;
            float4 v = *(const float4*)(Wp + (size_t)(kb + k) * OUTD + n4 * 4);
            Bs2[k][n4*2+0] = pk2(v.x, v.y);
            Bs2[k][n4*2+1] = pk2(v.z, v.w);
        }
        __syncthreads();
        #pragma unroll
        for (int k = 0; k < 16; k++) {
            u64 rb[4];
            #pragma unroll
            for (int j = 0; j < 4; j++) rb[j] = Bs2[k][tx + 16*j];
            #pragma unroll
            for (int i = 0; i < 8; i++) {
                float a = As[k][ty*8 + i];
                u64 a2 = pk2(a, a);
                #pragma unroll
                for (int j = 0; j < 4; j++) acc2[i][j] = fma2(a2, rb[j], acc2[i][j]);
            }
        }
        __syncthreads();
    }
    float blo[4], bhi[4];
    #pragma unroll
    for (int j = 0; j < 4; j++) {
        int c = 2*(tx + 16*j);
        blo[j] = bp[c]; bhi[j] = bp[c+1];
    }
    #pragma unroll
    for (int i = 0; i < 8; i++) {
        size_t row = (size_t)(rowBase + ty*8 + i);
        #pragma unroll
        for (int j = 0; j < 4; j++) {
            float lo, hi;
            upk2(lo, hi, acc2[i][j]);
            float v0 = lo + blo[j], v1 = hi + bhi[j];
            int c = 2*(tx + 16*j);
            *(u64*)(out + row*OUTD + c) = pk2(1.f/(1.f+expf(-v0)), 1.f/(1.f+expf(-v1)));
        }
    }
}

// ---------------- launch ----------------
extern "C" void kernel_launch(void* const* d_in, const int* in_sizes, int n_in,
                              void* d_out, int out_size) {
    const float* x   = (const float*)d_in[0];
    const float* Mk  = (const float*)d_in[1];
    const float* Mv0 = (const float*)d_in[2];
    const float* Wr  = (const float*)d_in[3];
    const float* br  = (const float*)d_in[4];
    const float* Ww  = (const float*)d_in[5];
    const float* bw  = (const float*)d_in[6];
    const float* Wp  = (const float*)d_in[7];
    const float* bp  = (const float*)d_in[8];
    float* out = (float*)d_out;

    k0_fold<<<65, 256>>>(Wr, br, Mk);
    k1a_wsoftmax<<<ROWS/128, 256>>>(x);
    k1b_ea<<<ROWS/128, 256>>>(x, Ww, bw);
    k2_scan<<<Bb, 512>>>(Mv0);
    k3_out<<<ROWS/128, 256>>>(Wp, bp, out);
}